// round 5
// baseline (speedup 1.0000x reference)
#include <cuda_runtime.h>

// ---------------------------------------------------------------------------
// Problem constants
//   x      [32, 256, 32, 32] f32
//   weight [256, 256, 3, 3]  f32
//   gamma  [1024] f32, beta [1024] f32
//   out    [32, 256, 32, 32] f32
// ---------------------------------------------------------------------------

#define NB   32
#define NG   4
#define CIG  64
#define NCO  256
#define HW   32
#define TAPS 9

// scratch (device globals: allocation-free per harness rules)
static __device__ float g_ws[256 * 9 * 256];        // [cin][tap][co]  signed weights (±alpha)
static __device__ float g_psum[33554432];           // [b][g*256+co][h][w]
static __device__ float g_pA[1024 * 256];           // per-channel block partial sums
static __device__ float g_pQ[1024 * 256];           // per-channel block partial sum-of-squares
static __device__ float g_scale[1024];
static __device__ float g_bias[1024];

// ---- packed fp32x2 helpers (Blackwell) ----
__device__ __forceinline__ unsigned long long ffma2(unsigned long long a,
                                                    unsigned long long b,
                                                    unsigned long long c) {
    unsigned long long d;
    asm("fma.rn.f32x2 %0, %1, %2, %3;" : "=l"(d) : "l"(a), "l"(b), "l"(c));
    return d;
}
__device__ __forceinline__ unsigned long long pack2(float v) {
    unsigned long long d;
    asm("mov.b64 %0, {%1, %1};" : "=l"(d) : "f"(v));
    return d;
}
__device__ __forceinline__ unsigned long long packab(float a, float b) {
    unsigned long long d;
    asm("mov.b64 %0, {%1, %2};" : "=l"(d) : "f"(a), "f"(b));
    return d;
}

// ---------------------------------------------------------------------------
// K0: alpha[co] = mean |w[co,:,:,:]|  and signed-weight repack into
//     g_ws[(cin*9 + tap)*256 + co] = sign(w[co][cin][tap]) * alpha[co]
// One block per output channel.
// ---------------------------------------------------------------------------
__global__ void k_prep(const float* __restrict__ w) {
    const int co = blockIdx.x;
    const int t  = threadIdx.x;          // 256 threads
    __shared__ float red[256];
    const float* wc = w + co * 2304;     // 256*9 weights for this co
    float s = 0.0f;
    for (int i = t; i < 2304; i += 256) s += fabsf(wc[i]);
    red[t] = s;
    __syncthreads();
    for (int off = 128; off; off >>= 1) {
        if (t < off) red[t] += red[t + off];
        __syncthreads();
    }
    const float alpha = red[0] * (1.0f / 2304.0f);
    for (int i = t; i < 2304; i += 256) {
        const int cin = i / 9;
        const int tap = i - cin * 9;
        const float v = wc[i];
        g_ws[(cin * 9 + tap) * 256 + co] = (v >= 0.0f) ? alpha : -alpha;
    }
}

// ---------------------------------------------------------------------------
// K1: binary-weight conv (fp32, packed f32x2 FMA).
// Block = (co-tile 64, row-tile 4, (b,g)). 256 threads = 16 co-threads x 16
// pixel-threads; each thread: 4 co x 8 cols, acc as 2 co-pairs x 8 pixels.
// SMEM: x slab [64ci][6 rows][36 cols] (55KB) + weights [64ci][9tap][64co] (144KB)
// Also writes deterministic per-(channel, block) partial sum / sumsq.
// ---------------------------------------------------------------------------
__global__ void __launch_bounds__(256, 1)
k_conv(const float* __restrict__ x) {
    extern __shared__ float smem[];
    float* sx = smem;              // 13824 floats
    float* sw = smem + 13824;      // 36864 floats

    const int b    = blockIdx.z >> 2;
    const int g    = blockIdx.z & 3;
    const int rowt = blockIdx.y;           // 0..7
    const int cot  = blockIdx.x;           // 0..3
    const int r0     = rowt * 4;
    const int coBase = cot * 64;
    const int tid  = threadIdx.x;

    // ---- stage x slab: rows r0-1..r0+4, cols -1..34 (zero padded) ----
    const float* xg = x + (b * 256 + g * 64) * 1024;
    for (int i = tid; i < 64 * 6 * 36; i += 256) {
        const int ci  = i / 216;
        const int rem = i - ci * 216;
        const int lr  = rem / 36;
        const int lc  = rem - lr * 36;
        const int gr  = r0 - 1 + lr;
        const int gc  = lc - 1;
        float v = 0.0f;
        if ((unsigned)gr < 32u && (unsigned)gc < 32u)
            v = xg[ci * 1024 + gr * 32 + gc];
        sx[i] = v;
    }
    // ---- stage weights: [ci*9+tap][64 co] ----
    const float* wsg = g_ws + (g * 64) * 9 * 256 + coBase;
    for (int i = tid; i < 64 * 9 * 64; i += 256) {
        const int cit = i >> 6;    // ci*9 + tap
        const int co  = i & 63;
        sw[i] = wsg[cit * 256 + co];
    }
    __syncthreads();

    const int cothread = tid >> 4;          // 0..15
    const int pth      = tid & 15;          // 0..15
    const int prow     = pth >> 2;          // 0..3
    const int c0       = (pth & 3) << 3;    // 0,8,16,24
    const int cb       = cothread << 2;     // co within tile: cb..cb+3

    unsigned long long acc[2][8];
#pragma unroll
    for (int p = 0; p < 2; p++)
#pragma unroll
        for (int j = 0; j < 8; j++) acc[p][j] = 0ull;

    const float* xp0 = sx + prow * 36 + c0;
    const float* wp0 = sw + cb;

    for (int ci = 0; ci < 64; ci++) {
        const float* xp = xp0 + ci * 216;
        const float* wp = wp0 + ci * 576;
#pragma unroll
        for (int kh = 0; kh < 3; kh++) {
            const float4 va = *reinterpret_cast<const float4*>(xp + kh * 36);
            const float4 vb = *reinterpret_cast<const float4*>(xp + kh * 36 + 4);
            const float2 vc = *reinterpret_cast<const float2*>(xp + kh * 36 + 8);
            const float v[10] = {va.x, va.y, va.z, va.w,
                                 vb.x, vb.y, vb.z, vb.w,
                                 vc.x, vc.y};
            unsigned long long dup[10];
#pragma unroll
            for (int t2 = 0; t2 < 10; t2++) dup[t2] = pack2(v[t2]);
#pragma unroll
            for (int kw = 0; kw < 3; kw++) {
                const float4 w4 = *reinterpret_cast<const float4*>(wp + (kh * 3 + kw) * 64);
                const unsigned long long w01 = packab(w4.x, w4.y);
                const unsigned long long w23 = packab(w4.z, w4.w);
#pragma unroll
                for (int j = 0; j < 8; j++) {
                    acc[0][j] = ffma2(dup[kw + j], w01, acc[0][j]);
                    acc[1][j] = ffma2(dup[kw + j], w23, acc[1][j]);
                }
            }
        }
    }

    __syncthreads();   // about to reuse sx for the stats reduction

    const int row = r0 + prow;
    float sacc[4], qacc[4];
#pragma unroll
    for (int k = 0; k < 4; k++) {
        float vv[8];
#pragma unroll
        for (int j = 0; j < 8; j++) {
            float2 f2 = *reinterpret_cast<float2*>(&acc[k >> 1][j]);
            vv[j] = (k & 1) ? f2.y : f2.x;
        }
        const int chan = g * 256 + coBase + cb + k;
        float* po = g_psum + ((b * 1024 + chan) * 1024 + row * 32 + c0);
        float4 o0 = make_float4(vv[0], vv[1], vv[2], vv[3]);
        float4 o1 = make_float4(vv[4], vv[5], vv[6], vv[7]);
        *reinterpret_cast<float4*>(po)     = o0;
        *reinterpret_cast<float4*>(po + 4) = o1;
        float s = 0.0f, q = 0.0f;
#pragma unroll
        for (int j = 0; j < 8; j++) { s += vv[j]; q += vv[j] * vv[j]; }
        sacc[k] = s;
        qacc[k] = q;
    }

    float* redS = sx;            // 1024 floats
    float* redQ = sx + 1024;     // 1024 floats
#pragma unroll
    for (int k = 0; k < 4; k++) {
        redS[(cb + k) * 16 + pth] = sacc[k];
        redQ[(cb + k) * 16 + pth] = qacc[k];
    }
    __syncthreads();
    if (tid < 64) {
        float s = 0.0f, q = 0.0f;
#pragma unroll
        for (int p = 0; p < 16; p++) {
            s += redS[tid * 16 + p];
            q += redQ[tid * 16 + p];
        }
        const int chan = g * 256 + coBase + tid;
        const int slot = b * 8 + rowt;           // 0..255
        g_pA[chan * 256 + slot] = s;
        g_pQ[chan * 256 + slot] = q;
    }
}

// ---------------------------------------------------------------------------
// K2: finalize per-channel BN stats -> scale/bias. One block per channel.
// ---------------------------------------------------------------------------
__global__ void k_stats(const float* __restrict__ gamma,
                        const float* __restrict__ beta) {
    const int ch = blockIdx.x;
    const int t  = threadIdx.x;    // 256
    __shared__ float rs[256], rq[256];
    rs[t] = g_pA[ch * 256 + t];
    rq[t] = g_pQ[ch * 256 + t];
    __syncthreads();
    for (int off = 128; off; off >>= 1) {
        if (t < off) { rs[t] += rs[t + off]; rq[t] += rq[t + off]; }
        __syncthreads();
    }
    if (t == 0) {
        const float mean = rs[0] * (1.0f / 32768.0f);
        const float var  = rq[0] * (1.0f / 32768.0f) - mean * mean;
        const float inv  = gamma[ch] / sqrtf(var + 1e-5f);
        g_scale[ch] = inv;
        g_bias[ch]  = beta[ch] - mean * inv;
    }
}

// ---------------------------------------------------------------------------
// K3: threshold (sign of BN output) + merge 4 groups + qrelu LUT.
// float4 vectorized over w.
// ---------------------------------------------------------------------------
__global__ void k_out(float* __restrict__ out) {
    const int idx = blockIdx.x * 256 + threadIdx.x;   // quad index, 2,097,152 total
    const int b    = idx >> 16;          // 65536 quads per batch
    const int qb   = idx & 65535;
    const int co   = qb >> 8;            // 256 quads per (b,co)
    const int pix4 = qb & 255;

    const float4* pb = reinterpret_cast<const float4*>(g_psum);
    int c0 = 0, c1 = 0, c2 = 0, c3 = 0;
#pragma unroll
    for (int g = 0; g < 4; g++) {
        const int chan = g * 256 + co;
        const float4 p = pb[(b * 1024 + chan) * 256 + pix4];
        const float sc = g_scale[chan];
        const float bi = g_bias[chan];
        c0 += (p.x * sc + bi >= 0.0f);
        c1 += (p.y * sc + bi >= 0.0f);
        c2 += (p.z * sc + bi >= 0.0f);
        c3 += (p.w * sc + bi >= 0.0f);
    }
    // y = 2*cnt - 4; q = round(clip(y/4,0,1)*15)/15*4  ->  {0,0,0, 8/15*4, 4}
    const float Q3 = (8.0f / 15.0f) * 4.0f;
    float4 o;
    o.x = (c0 == 4) ? 4.0f : ((c0 == 3) ? Q3 : 0.0f);
    o.y = (c1 == 4) ? 4.0f : ((c1 == 3) ? Q3 : 0.0f);
    o.z = (c2 == 4) ? 4.0f : ((c2 == 3) ? Q3 : 0.0f);
    o.w = (c3 == 4) ? 4.0f : ((c3 == 3) ? Q3 : 0.0f);
    reinterpret_cast<float4*>(out)[idx] = o;
}

// ---------------------------------------------------------------------------
extern "C" void kernel_launch(void* const* d_in, const int* in_sizes, int n_in,
                              void* d_out, int out_size) {
    const float* x      = (const float*)d_in[0];
    const float* weight = (const float*)d_in[1];
    const float* gamma  = (const float*)d_in[2];
    const float* beta   = (const float*)d_in[3];
    float* out = (float*)d_out;

    const int smem_conv = (13824 + 36864) * (int)sizeof(float);   // 202752 B
    cudaFuncSetAttribute(k_conv, cudaFuncAttributeMaxDynamicSharedMemorySize, smem_conv);

    k_prep<<<256, 256>>>(weight);
    k_conv<<<dim3(4, 8, NB * NG), 256, smem_conv>>>(x);
    k_stats<<<1024, 256>>>(gamma, beta);
    k_out<<<8192, 256>>>(out);
}